// round 1
// baseline (speedup 1.0000x reference)
#include <cuda_runtime.h>
#include <cstddef>

#define N_NODES 100000
#define F_IN    512
#define F_MID   256
#define NGRAPH  256
#define EPS_GN  1e-5f

// ---------------- device scratch (no allocations allowed) ----------------
__device__ float g_buf1[(size_t)N_NODES * F_MID];   // x1 -> x2
__device__ float g_buf2[(size_t)N_NODES * F_MID];   // h  -> x3
__device__ float g_alpha[NGRAPH * F_IN];
__device__ float g_beta [NGRAPH * F_IN];
__device__ int   g_segstart[NGRAPH + 1];
__device__ float g_part[2 * 256 * F_MID];           // deterministic global-stat partials
__device__ int   g_is64;

// ---------------- batch dtype detection (int32 vs int64) ----------------
__global__ void k_detect(const int* b32, int n64) {
    __shared__ int found;
    if (threadIdx.x == 0) found = 0;
    __syncthreads();
    for (int i = threadIdx.x; i < n64; i += blockDim.x) {
        if (b32[2 * i + 1] != 0) { found = 1; break; }
    }
    __syncthreads();
    if (threadIdx.x == 0) g_is64 = found ? 0 : 1;
}

__device__ __forceinline__ int get_batch(const void* bp, int r) {
    return g_is64 ? (int)((const long long*)bp)[r] : ((const int*)bp)[r];
}

// ---------------- segment bounds (batch is sorted) ----------------
__global__ void k_segbounds(const void* bp, int n) {
    int g = threadIdx.x;
    if (g > NGRAPH) return;
    if (g == NGRAPH) { g_segstart[g] = n; return; }
    int lo = 0, hi = n;
    while (lo < hi) {
        int mid = (lo + hi) >> 1;
        if (get_batch(bp, mid) < g) lo = mid + 1; else hi = mid;
    }
    g_segstart[g] = lo;
}

// ---------------- per-graph stats -> folded affine (alpha, beta) ----------------
__global__ void k_segstats(const float* __restrict__ x, int F,
                           const float* __restrict__ w, const float* __restrict__ b,
                           const float* __restrict__ ms,
                           float* __restrict__ alpha, float* __restrict__ beta) {
    int g = blockIdx.x;
    int f = blockIdx.y * blockDim.x + threadIdx.x;
    int s = g_segstart[g], e = g_segstart[g + 1];
    float sum = 0.f, sq = 0.f;
    for (int r = s; r < e; r++) {
        float v = x[(size_t)r * F + f];
        sum += v; sq += v * v;
    }
    float cnt  = fmaxf((float)(e - s), 1.f);
    float m    = sum / cnt;
    float ex2  = sq / cnt;
    float msv  = ms[f];
    float var  = ex2 - m * m * msv * (2.f - msv);
    float rstd = rsqrtf(var + EPS_GN);
    float wa   = w[f] * rstd;
    alpha[g * F + f] = wa;
    beta [g * F + f] = b[f] - wa * msv * m;
}

// ---------------- global stats (gn3), deterministic two-stage ----------------
__global__ void k_gstats_acc(const float* __restrict__ x, int N) {
    int f = threadIdx.x;                 // F_MID threads
    int chunk = (N + gridDim.x - 1) / gridDim.x;
    int r0 = blockIdx.x * chunk;
    int r1 = min(r0 + chunk, N);
    float sum = 0.f, sq = 0.f;
    for (int r = r0; r < r1; r++) {
        float v = x[(size_t)r * F_MID + f];
        sum += v; sq += v * v;
    }
    g_part[blockIdx.x * F_MID + f] = sum;
    g_part[256 * F_MID + blockIdx.x * F_MID + f] = sq;
}

__global__ void k_gstats_fin(const float* __restrict__ w, const float* __restrict__ b,
                             const float* __restrict__ ms,
                             float* __restrict__ alpha, float* __restrict__ beta, float cnt) {
    int f = threadIdx.x;
    float sum = 0.f, sq = 0.f;
    for (int i = 0; i < 256; i++) {
        sum += g_part[i * F_MID + f];
        sq  += g_part[256 * F_MID + i * F_MID + f];
    }
    float m    = sum / cnt;
    float ex2  = sq / cnt;
    float msv  = ms[f];
    float var  = ex2 - m * m * msv * (2.f - msv);
    float rstd = rsqrtf(var + EPS_GN);
    float wa   = w[f] * rstd;
    alpha[f] = wa;                       // row 0 used for all nodes
    beta [f] = b[f] - wa * msv * m;
}

// ---------------- fused (norm [+prelu]) @ W^T + bias [+ residual avg] ----------------
#define BM 128
#define BN 128
#define BKK 16

template<bool PRELU, bool RESID, bool GLOBALN>
__global__ void __launch_bounds__(256)
k_gemm(const float* __restrict__ A, const float* __restrict__ W,
       const float* __restrict__ bias,
       const float* __restrict__ alpha, const float* __restrict__ beta,
       const void* __restrict__ batchp, const float* __restrict__ slope_ptr,
       const float* resid, float* out,
       int N, int K, int Nout) {
    __shared__ float As[BKK][BM + 4];
    __shared__ float Ws[BKK][BN + 4];
    int tid = threadIdx.x;
    int tx = tid & 15, ty = tid >> 4;
    int bm0 = blockIdx.x * BM, bn0 = blockIdx.y * BN;
    float slope = PRELU ? *slope_ptr : 0.f;

    float acc[8][8];
    #pragma unroll
    for (int i = 0; i < 8; i++)
        #pragma unroll
        for (int j = 0; j < 8; j++) acc[i][j] = 0.f;

    for (int kt = 0; kt < K; kt += BKK) {
        // --- A tile: fused normalize (+prelu) ---
        #pragma unroll
        for (int l = 0; l < 2; l++) {
            int v   = tid * 2 + l;
            int row = v >> 2;
            int kk  = (v & 3) * 4;
            int r   = bm0 + row;
            float4 val = make_float4(0.f, 0.f, 0.f, 0.f);
            if (r < N) {
                int g = GLOBALN ? 0 : get_batch(batchp, r);
                float4 xv = *(const float4*)(A     + (size_t)r * K + kt + kk);
                float4 al = *(const float4*)(alpha + (size_t)g * K + kt + kk);
                float4 be = *(const float4*)(beta  + (size_t)g * K + kt + kk);
                val.x = fmaf(xv.x, al.x, be.x);
                val.y = fmaf(xv.y, al.y, be.y);
                val.z = fmaf(xv.z, al.z, be.z);
                val.w = fmaf(xv.w, al.w, be.w);
                if (PRELU) {
                    val.x = val.x >= 0.f ? val.x : slope * val.x;
                    val.y = val.y >= 0.f ? val.y : slope * val.y;
                    val.z = val.z >= 0.f ? val.z : slope * val.z;
                    val.w = val.w >= 0.f ? val.w : slope * val.w;
                }
            }
            As[kk + 0][row] = val.x;
            As[kk + 1][row] = val.y;
            As[kk + 2][row] = val.z;
            As[kk + 3][row] = val.w;
        }
        // --- W tile ---
        #pragma unroll
        for (int l = 0; l < 2; l++) {
            int v  = tid * 2 + l;
            int n  = v >> 2;
            int kk = (v & 3) * 4;
            float4 wv = *(const float4*)(W + (size_t)(bn0 + n) * K + kt + kk);
            Ws[kk + 0][n] = wv.x;
            Ws[kk + 1][n] = wv.y;
            Ws[kk + 2][n] = wv.z;
            Ws[kk + 3][n] = wv.w;
        }
        __syncthreads();
        #pragma unroll
        for (int k = 0; k < BKK; k++) {
            float af[8], bf[8];
            #pragma unroll
            for (int i = 0; i < 8; i++) af[i] = As[k][i * 16 + ty];
            #pragma unroll
            for (int j = 0; j < 8; j++) bf[j] = Ws[k][j * 16 + tx];
            #pragma unroll
            for (int i = 0; i < 8; i++)
                #pragma unroll
                for (int j = 0; j < 8; j++)
                    acc[i][j] = fmaf(af[i], bf[j], acc[i][j]);
        }
        __syncthreads();
    }
    // --- epilogue ---
    #pragma unroll
    for (int i = 0; i < 8; i++) {
        int r = bm0 + i * 16 + ty;
        if (r >= N) continue;
        #pragma unroll
        for (int j = 0; j < 8; j++) {
            int n = bn0 + j * 16 + tx;
            float c = acc[i][j] + bias[n];
            if (RESID) c = (c + resid[(size_t)r * Nout + n]) * 0.5f;
            out[(size_t)r * Nout + n] = c;
        }
    }
}

// ---------------- launch ----------------
extern "C" void kernel_launch(void* const* d_in, const int* in_sizes, int n_in,
                              void* d_out, int out_size) {
    const float* x      = (const float*)d_in[0];
    const void*  batch  = d_in[1];
    const float* gn1_w = (const float*)d_in[2],  *gn1_b = (const float*)d_in[3],  *gn1_ms = (const float*)d_in[4];
    const float* gn2_w = (const float*)d_in[5],  *gn2_b = (const float*)d_in[6],  *gn2_ms = (const float*)d_in[7];
    const float* gn3_w = (const float*)d_in[8],  *gn3_b = (const float*)d_in[9],  *gn3_ms = (const float*)d_in[10];
    const float* gn4_w = (const float*)d_in[11], *gn4_b = (const float*)d_in[12], *gn4_ms = (const float*)d_in[13];
    const float* gn5_w = (const float*)d_in[14], *gn5_b = (const float*)d_in[15], *gn5_ms = (const float*)d_in[16];
    const float* lin1_W = (const float*)d_in[17], *lin1_b = (const float*)d_in[18];
    const float* lin2_W = (const float*)d_in[19], *lin2_b = (const float*)d_in[20];
    const float* lin3_W = (const float*)d_in[21], *lin3_b = (const float*)d_in[22];
    const float* lin4_W = (const float*)d_in[23], *lin4_b = (const float*)d_in[24];
    const float* lin5_W = (const float*)d_in[25], *lin5_b = (const float*)d_in[26];
    const float* a2 = (const float*)d_in[27];
    const float* a3 = (const float*)d_in[28];
    const float* a4 = (const float*)d_in[29];
    const float* a5 = (const float*)d_in[30];
    float* out = (float*)d_out;

    float *buf1, *buf2, *alpha, *beta;
    cudaGetSymbolAddress((void**)&buf1,  g_buf1);
    cudaGetSymbolAddress((void**)&buf2,  g_buf2);
    cudaGetSymbolAddress((void**)&alpha, g_alpha);
    cudaGetSymbolAddress((void**)&beta,  g_beta);

    k_detect<<<1, 1024>>>((const int*)batch, N_NODES / 2);
    k_segbounds<<<1, NGRAPH + 1>>>(batch, N_NODES);

    dim3 gmid((N_NODES + BM - 1) / BM, F_MID / BN);
    dim3 gout((N_NODES + BM - 1) / BM, F_IN  / BN);

    // stage 1: x1 = gn1(x) @ W1^T + b1
    k_segstats<<<dim3(NGRAPH, F_IN / 256), 256>>>(x, F_IN, gn1_w, gn1_b, gn1_ms, alpha, beta);
    k_gemm<false, false, false><<<gmid, 256>>>(x, lin1_W, lin1_b, alpha, beta, batch,
                                               nullptr, nullptr, buf1, N_NODES, F_IN, F_MID);
    // stage 2: h = prelu(gn2(x1)) @ W2^T + b2
    k_segstats<<<dim3(NGRAPH, 1), 256>>>(buf1, F_MID, gn2_w, gn2_b, gn2_ms, alpha, beta);
    k_gemm<true, false, false><<<gmid, 256>>>(buf1, lin2_W, lin2_b, alpha, beta, batch,
                                              a2, nullptr, buf2, N_NODES, F_MID, F_MID);
    // stage 3 (global norm): x2 = (prelu(gn3g(h)) @ W3^T + b3 + x1)/2  (in-place into buf1)
    k_gstats_acc<<<256, F_MID>>>(buf2, N_NODES);
    k_gstats_fin<<<1, F_MID>>>(gn3_w, gn3_b, gn3_ms, alpha, beta, (float)N_NODES);
    k_gemm<true, true, true><<<gmid, 256>>>(buf2, lin3_W, lin3_b, alpha, beta, nullptr,
                                            a3, buf1, buf1, N_NODES, F_MID, F_MID);
    // stage 4: x3 = (prelu(gn4(x2)) @ W4^T + b4 + x2)/2  -> buf2
    k_segstats<<<dim3(NGRAPH, 1), 256>>>(buf1, F_MID, gn4_w, gn4_b, gn4_ms, alpha, beta);
    k_gemm<true, true, false><<<gmid, 256>>>(buf1, lin4_W, lin4_b, alpha, beta, batch,
                                             a4, buf1, buf2, N_NODES, F_MID, F_MID);
    // stage 5: out = prelu(gn5(x3)) @ W5^T + b5
    k_segstats<<<dim3(NGRAPH, 1), 256>>>(buf2, F_MID, gn5_w, gn5_b, gn5_ms, alpha, beta);
    k_gemm<true, false, false><<<gout, 256>>>(buf2, lin5_W, lin5_b, alpha, beta, batch,
                                              a5, nullptr, out, N_NODES, F_MID, F_IN);
    (void)in_sizes; (void)n_in; (void)out_size;
}

// round 5
// speedup vs baseline: 1.7907x; 1.7907x over previous
#include <cuda_runtime.h>
#include <cuda_bf16.h>
#include <cstdint>
#include <cstddef>

#define N_NODES 100000
#define F_IN    512
#define F_MID   256
#define NGRAPH  256
#define EPS_GN  1e-5f
#define GRID_M  ((N_NODES + 127) / 128)

// ---------------- device scratch (no allocations allowed) ----------------
__device__ float g_buf1[(size_t)N_NODES * F_MID];
__device__ float g_buf2[(size_t)N_NODES * F_MID];
__device__ float g_alpha[NGRAPH * F_IN];
__device__ float g_beta [NGRAPH * F_IN];
__device__ int   g_segstart[NGRAPH + 1];
__device__ float g_part[2 * 256 * F_MID];
__device__ int   g_is64;

#define W_TOT (F_MID*F_IN + 3*F_MID*F_MID + F_IN*F_MID)
__device__ __nv_bfloat16 g_whi[W_TOT];
__device__ __nv_bfloat16 g_wlo[W_TOT];
#define WO1 0
#define WO2 (F_MID*F_IN)
#define WO3 (WO2 + F_MID*F_MID)
#define WO4 (WO3 + F_MID*F_MID)
#define WO5 (WO4 + F_MID*F_MID)

// ---------------- helpers ----------------
__device__ __forceinline__ uint32_t smem_u32(const void* p) {
    uint32_t a;
    asm("{ .reg .u64 t; cvta.to.shared.u64 t, %1; cvt.u32.u64 %0, t; }" : "=r"(a) : "l"(p));
    return a;
}

#define LDSM_X4(r0,r1,r2,r3,addr) \
    asm volatile("ldmatrix.sync.aligned.m8n8.x4.shared.b16 {%0,%1,%2,%3}, [%4];" \
        : "=r"(r0),"=r"(r1),"=r"(r2),"=r"(r3) : "r"(addr))
#define LDSM_X2(r0,r1,addr) \
    asm volatile("ldmatrix.sync.aligned.m8n8.x2.shared.b16 {%0,%1}, [%2];" \
        : "=r"(r0),"=r"(r1) : "r"(addr))
#define MMA16816(c, a0,a1,a2,a3, b0,b1) \
    asm volatile("mma.sync.aligned.m16n8k16.row.col.f32.bf16.bf16.f32 " \
        "{%0,%1,%2,%3}, {%4,%5,%6,%7}, {%8,%9}, {%0,%1,%2,%3};" \
        : "+f"((c)[0]),"+f"((c)[1]),"+f"((c)[2]),"+f"((c)[3]) \
        : "r"(a0),"r"(a1),"r"(a2),"r"(a3), "r"(b0),"r"(b1))

__device__ __forceinline__ uint32_t pack_bf2(float a, float b) {
    __nv_bfloat162 p;
    p.x = __float2bfloat16_rn(a);
    p.y = __float2bfloat16_rn(b);
    return *reinterpret_cast<uint32_t*>(&p);
}

// ---------------- batch dtype detection ----------------
__global__ void k_detect(const int* b32, int n64) {
    __shared__ int found;
    if (threadIdx.x == 0) found = 0;
    __syncthreads();
    for (int i = threadIdx.x; i < n64; i += blockDim.x)
        if (b32[2 * i + 1] != 0) { found = 1; break; }
    __syncthreads();
    if (threadIdx.x == 0) g_is64 = found ? 0 : 1;
}
__device__ __forceinline__ int get_batch(const void* bp, int r) {
    return g_is64 ? (int)((const long long*)bp)[r] : ((const int*)bp)[r];
}

__global__ void k_segbounds(const void* bp, int n) {
    int g = threadIdx.x;
    if (g > NGRAPH) return;
    if (g == NGRAPH) { g_segstart[g] = n; return; }
    int lo = 0, hi = n;
    while (lo < hi) { int mid = (lo + hi) >> 1; if (get_batch(bp, mid) < g) lo = mid + 1; else hi = mid; }
    g_segstart[g] = lo;
}

// ---------------- per-graph stats -> folded affine ----------------
__global__ void k_segstats(const float* __restrict__ x, int F,
                           const float* __restrict__ w, const float* __restrict__ b,
                           const float* __restrict__ ms,
                           float* __restrict__ alpha, float* __restrict__ beta) {
    int g = blockIdx.x;
    int f = blockIdx.y * blockDim.x + threadIdx.x;
    int s = g_segstart[g], e = g_segstart[g + 1];
    float sum = 0.f, sq = 0.f;
    for (int r = s; r < e; r++) { float v = x[(size_t)r * F + f]; sum += v; sq += v * v; }
    float cnt = fmaxf((float)(e - s), 1.f);
    float m = sum / cnt, ex2 = sq / cnt, msv = ms[f];
    float var = ex2 - m * m * msv * (2.f - msv);
    float rstd = rsqrtf(var + EPS_GN);
    float wa = w[f] * rstd;
    alpha[g * F + f] = wa;
    beta [g * F + f] = b[f] - wa * msv * m;
}

// ---------------- global stats (gn3) ----------------
__global__ void k_gstats_acc(const float* __restrict__ x, int N) {
    int f = threadIdx.x;
    int chunk = (N + gridDim.x - 1) / gridDim.x;
    int r0 = blockIdx.x * chunk, r1 = min(r0 + chunk, N);
    float sum = 0.f, sq = 0.f;
    for (int r = r0; r < r1; r++) { float v = x[(size_t)r * F_MID + f]; sum += v; sq += v * v; }
    g_part[blockIdx.x * F_MID + f] = sum;
    g_part[256 * F_MID + blockIdx.x * F_MID + f] = sq;
}
__global__ void k_gstats_fin(const float* __restrict__ w, const float* __restrict__ b,
                             const float* __restrict__ ms,
                             float* __restrict__ alpha, float* __restrict__ beta, float cnt) {
    int f = threadIdx.x;
    float sum = 0.f, sq = 0.f;
    for (int i = 0; i < 256; i++) { sum += g_part[i * F_MID + f]; sq += g_part[256 * F_MID + i * F_MID + f]; }
    float m = sum / cnt, ex2 = sq / cnt, msv = ms[f];
    float var = ex2 - m * m * msv * (2.f - msv);
    float rstd = rsqrtf(var + EPS_GN);
    float wa = w[f] * rstd;
    alpha[f] = wa;
    beta [f] = b[f] - wa * msv * m;
}

// ---------------- weight split fp32 -> bf16 hi/lo ----------------
__global__ void k_wsplit(const float* __restrict__ W, __nv_bfloat16* hi, __nv_bfloat16* lo, int n) {
    int i = blockIdx.x * blockDim.x + threadIdx.x;
    if (i >= n) return;
    float v = W[i];
    __nv_bfloat16 h = __float2bfloat16_rn(v);
    hi[i] = h;
    lo[i] = __float2bfloat16_rn(v - __bfloat162float(h));
}

// ---------------- HMMA (mma.sync) fused GEMM ----------------
// CTA tile 128x128, BK=32, 8 warps (2 M x 4 N), warp tile 64x32.
// SMEM per buffer (bytes): Ahi 10240 | Alo 10240 | Bhi 10240 | Blo 10240 = 40960; x2 buffers.
// Row pitch 40 bf16 = 80 B (conflict-free ldmatrix + STS).
#define BUF_B   40960
#define SMEM_SZ (2 * BUF_B)

template<bool PRELU, bool RESID, bool GLOBALN>
__global__ void __launch_bounds__(256, 1)
k_mma(const float* __restrict__ A,
      const __nv_bfloat16* __restrict__ Whi, const __nv_bfloat16* __restrict__ Wlo,
      const float* __restrict__ bias,
      const float* __restrict__ alpha, const float* __restrict__ beta,
      const void* __restrict__ batchp, const float* __restrict__ slope_ptr,
      const float* __restrict__ resid, float* __restrict__ out,
      int N, int K, int Nout) {
    extern __shared__ char sm[];
    uint32_t sbase = smem_u32(sm);

    int tid = threadIdx.x, wid = tid >> 5, lane = tid & 31;
    int bm0 = blockIdx.x * 128, bn0 = blockIdx.y * 128;
    int NC = K >> 5;
    float slope = PRELU ? *slope_ptr : 0.f;
    int wm = (wid >> 2) * 64;    // 0 or 64
    int wn = (wid & 3) * 32;     // 0,32,64,96

    float acc[4][4][4];
    #pragma unroll
    for (int i = 0; i < 4; i++)
        #pragma unroll
        for (int j = 0; j < 4; j++)
            #pragma unroll
            for (int q = 0; q < 4; q++) acc[i][j][q] = 0.f;

    auto fill = [&](int c) {
        int kt = c << 5;
        char* buf = sm + (c & 1) * BUF_B;
        // ---- A: norm (+prelu) + bf16 split ----
        #pragma unroll
        for (int i = 0; i < 4; i++) {
            int id = tid + i * 256;          // 0..1023
            int row = id >> 3;               // 0..127
            int kq = id & 7;                 // float4 index
            int r = bm0 + row;
            int kk = kt + kq * 4;
            float4 v = make_float4(0.f, 0.f, 0.f, 0.f);
            if (r < N) {
                int g = GLOBALN ? 0 : get_batch(batchp, r);
                float4 xv = *(const float4*)(A + (size_t)r * K + kk);
                float4 al = *(const float4*)(alpha + (size_t)g * K + kk);
                float4 be = *(const float4*)(beta  + (size_t)g * K + kk);
                v.x = fmaf(xv.x, al.x, be.x); v.y = fmaf(xv.y, al.y, be.y);
                v.z = fmaf(xv.z, al.z, be.z); v.w = fmaf(xv.w, al.w, be.w);
                if (PRELU) {
                    v.x = v.x >= 0.f ? v.x : slope * v.x;
                    v.y = v.y >= 0.f ? v.y : slope * v.y;
                    v.z = v.z >= 0.f ? v.z : slope * v.z;
                    v.w = v.w >= 0.f ? v.w : slope * v.w;
                }
            }
            float hx = __bfloat162float(__float2bfloat16_rn(v.x));
            float hy = __bfloat162float(__float2bfloat16_rn(v.y));
            float hz = __bfloat162float(__float2bfloat16_rn(v.z));
            float hw = __bfloat162float(__float2bfloat16_rn(v.w));
            uint2 hv, lv;
            hv.x = pack_bf2(v.x, v.y);          hv.y = pack_bf2(v.z, v.w);
            lv.x = pack_bf2(v.x - hx, v.y - hy); lv.y = pack_bf2(v.z - hz, v.w - hw);
            uint32_t off = (uint32_t)(row * 80 + kq * 8);
            *(uint2*)(buf + off)         = hv;
            *(uint2*)(buf + 10240 + off) = lv;
        }
        // ---- B: pre-split weights ----
        #pragma unroll
        for (int i = 0; i < 2; i++) {
            int id = tid + i * 256;          // 0..511
            int n = id >> 2;                 // 0..127
            int q = id & 3;                  // 16B unit
            size_t gix = (size_t)(bn0 + n) * K + kt + q * 8;
            uint4 hv = *(const uint4*)(Whi + gix);
            uint4 lv = *(const uint4*)(Wlo + gix);
            uint32_t off = (uint32_t)(n * 80 + q * 16);
            *(uint4*)(buf + 20480 + off) = hv;
            *(uint4*)(buf + 30720 + off) = lv;
        }
    };

    fill(0);
    __syncthreads();

    for (int c = 0; c < NC; c++) {
        if (c + 1 < NC) fill(c + 1);
        uint32_t abase = sbase + (c & 1) * BUF_B;
        #pragma unroll
        for (int kk = 0; kk < 32; kk += 16) {
            uint32_t ah[4][4], alr[4][4], bh[4][2], bl[4][2];
            #pragma unroll
            for (int mt = 0; mt < 4; mt++) {
                uint32_t ad = abase + (uint32_t)((wm + mt * 16 + (lane & 15)) * 80
                              + (kk + ((lane >> 4) << 3)) * 2);
                LDSM_X4(ah[mt][0], ah[mt][1], ah[mt][2], ah[mt][3], ad);
                LDSM_X4(alr[mt][0], alr[mt][1], alr[mt][2], alr[mt][3], ad + 10240);
            }
            #pragma unroll
            for (int nt = 0; nt < 4; nt++) {
                uint32_t bd = abase + 20480 + (uint32_t)((wn + nt * 8 + (lane & 7)) * 80
                              + (kk + (((lane >> 3) & 1) << 3)) * 2);
                LDSM_X2(bh[nt][0], bh[nt][1], bd);
                LDSM_X2(bl[nt][0], bl[nt][1], bd + 10240);
            }
            #pragma unroll
            for (int mt = 0; mt < 4; mt++)
                #pragma unroll
                for (int nt = 0; nt < 4; nt++) {
                    MMA16816(acc[mt][nt], ah[mt][0], ah[mt][1], ah[mt][2], ah[mt][3], bh[nt][0], bh[nt][1]);
                    MMA16816(acc[mt][nt], ah[mt][0], ah[mt][1], ah[mt][2], ah[mt][3], bl[nt][0], bl[nt][1]);
                    MMA16816(acc[mt][nt], alr[mt][0], alr[mt][1], alr[mt][2], alr[mt][3], bh[nt][0], bh[nt][1]);
                }
        }
        __syncthreads();
    }

    // ---- epilogue ----
    #pragma unroll
    for (int mt = 0; mt < 4; mt++) {
        int r0 = bm0 + wm + mt * 16 + (lane >> 2);
        #pragma unroll
        for (int nt = 0; nt < 4; nt++) {
            int n = bn0 + wn + nt * 8 + 2 * (lane & 3);
            float2 bv = *(const float2*)(bias + n);
            float c0 = acc[mt][nt][0] + bv.x;
            float c1 = acc[mt][nt][1] + bv.y;
            float c2 = acc[mt][nt][2] + bv.x;
            float c3 = acc[mt][nt][3] + bv.y;
            if (r0 < N) {
                if (RESID) {
                    float2 rv = *(const float2*)(resid + (size_t)r0 * Nout + n);
                    c0 = (c0 + rv.x) * 0.5f; c1 = (c1 + rv.y) * 0.5f;
                }
                float2 o; o.x = c0; o.y = c1;
                *(float2*)(out + (size_t)r0 * Nout + n) = o;
            }
            int r1 = r0 + 8;
            if (r1 < N) {
                if (RESID) {
                    float2 rv = *(const float2*)(resid + (size_t)r1 * Nout + n);
                    c2 = (c2 + rv.x) * 0.5f; c3 = (c3 + rv.y) * 0.5f;
                }
                float2 o; o.x = c2; o.y = c3;
                *(float2*)(out + (size_t)r1 * Nout + n) = o;
            }
        }
    }
}

// ---------------- launch ----------------
extern "C" void kernel_launch(void* const* d_in, const int* in_sizes, int n_in,
                              void* d_out, int out_size) {
    const float* x     = (const float*)d_in[0];
    const void*  batch = d_in[1];
    const float* gn1_w = (const float*)d_in[2],  *gn1_b = (const float*)d_in[3],  *gn1_ms = (const float*)d_in[4];
    const float* gn2_w = (const float*)d_in[5],  *gn2_b = (const float*)d_in[6],  *gn2_ms = (const float*)d_in[7];
    const float* gn3_w = (const float*)d_in[8],  *gn3_b = (const float*)d_in[9],  *gn3_ms = (const float*)d_in[10];
    const float* gn4_w = (const float*)d_in[11], *gn4_b = (const float*)d_in[12], *gn4_ms = (const float*)d_in[13];
    const float* gn5_w = (const float*)d_in[14], *gn5_b = (const float*)d_in[15], *gn5_ms = (const float*)d_in[16];
    const float* lin1_W = (const float*)d_in[17], *lin1_b = (const float*)d_in[18];
    const float* lin2_W = (const float*)d_in[19], *lin2_b = (const float*)d_in[20];
    const float* lin3_W = (const float*)d_in[21], *lin3_b = (const float*)d_in[22];
    const float* lin4_W = (const float*)d_in[23], *lin4_b = (const float*)d_in[24];
    const float* lin5_W = (const float*)d_in[25], *lin5_b = (const float*)d_in[26];
    const float* a2 = (const float*)d_in[27];
    const float* a3 = (const float*)d_in[28];
    const float* a4 = (const float*)d_in[29];
    const float* a5 = (const float*)d_in[30];
    float* out = (float*)d_out;

    float *buf1, *buf2, *alpha, *beta;
    __nv_bfloat16 *whi, *wlo;
    cudaGetSymbolAddress((void**)&buf1,  g_buf1);
    cudaGetSymbolAddress((void**)&buf2,  g_buf2);
    cudaGetSymbolAddress((void**)&alpha, g_alpha);
    cudaGetSymbolAddress((void**)&beta,  g_beta);
    cudaGetSymbolAddress((void**)&whi,   g_whi);
    cudaGetSymbolAddress((void**)&wlo,   g_wlo);

    cudaFuncSetAttribute(k_mma<false, false, false>, cudaFuncAttributeMaxDynamicSharedMemorySize, SMEM_SZ);
    cudaFuncSetAttribute(k_mma<true,  false, false>, cudaFuncAttributeMaxDynamicSharedMemorySize, SMEM_SZ);
    cudaFuncSetAttribute(k_mma<true,  true,  true >, cudaFuncAttributeMaxDynamicSharedMemorySize, SMEM_SZ);
    cudaFuncSetAttribute(k_mma<true,  true,  false>, cudaFuncAttributeMaxDynamicSharedMemorySize, SMEM_SZ);

    k_detect<<<1, 1024>>>((const int*)batch, N_NODES / 2);
    k_segbounds<<<1, NGRAPH + 1>>>(batch, N_NODES);

    k_wsplit<<<(F_MID * F_IN  + 255) / 256, 256>>>(lin1_W, whi + WO1, wlo + WO1, F_MID * F_IN);
    k_wsplit<<<(F_MID * F_MID + 255) / 256, 256>>>(lin2_W, whi + WO2, wlo + WO2, F_MID * F_MID);
    k_wsplit<<<(F_MID * F_MID + 255) / 256, 256>>>(lin3_W, whi + WO3, wlo + WO3, F_MID * F_MID);
    k_wsplit<<<(F_MID * F_MID + 255) / 256, 256>>>(lin4_W, whi + WO4, wlo + WO4, F_MID * F_MID);
    k_wsplit<<<(F_IN  * F_MID + 255) / 256, 256>>>(lin5_W, whi + WO5, wlo + WO5, F_IN * F_MID);

    dim3 gmid(GRID_M, 2), gout(GRID_M, 4);

    // stage 1: x1 = gn1(x) @ W1^T + b1   (K=512)
    k_segstats<<<dim3(NGRAPH, 2), 256>>>(x, F_IN, gn1_w, gn1_b, gn1_ms, alpha, beta);
    k_mma<false, false, false><<<gmid, 256, SMEM_SZ>>>(x, whi + WO1, wlo + WO1, lin1_b,
        alpha, beta, batch, nullptr, nullptr, buf1, N_NODES, F_IN, F_MID);
    // stage 2: h = prelu(gn2(x1)) @ W2^T + b2
    k_segstats<<<dim3(NGRAPH, 1), 256>>>(buf1, F_MID, gn2_w, gn2_b, gn2_ms, alpha, beta);
    k_mma<true, false, false><<<gmid, 256, SMEM_SZ>>>(buf1, whi + WO2, wlo + WO2, lin2_b,
        alpha, beta, batch, a2, nullptr, buf2, N_NODES, F_MID, F_MID);
    // stage 3 (global norm): x2 = (prelu(gn3g(h)) @ W3^T + b3 + x1)/2 -> buf1
    k_gstats_acc<<<256, F_MID>>>(buf2, N_NODES);
    k_gstats_fin<<<1, F_MID>>>(gn3_w, gn3_b, gn3_ms, alpha, beta, (float)N_NODES);
    k_mma<true, true, true><<<gmid, 256, SMEM_SZ>>>(buf2, whi + WO3, wlo + WO3, lin3_b,
        alpha, beta, nullptr, a3, buf1, buf1, N_NODES, F_MID, F_MID);
    // stage 4: x3 = (prelu(gn4(x2)) @ W4^T + b4 + x2)/2 -> buf2
    k_segstats<<<dim3(NGRAPH, 1), 256>>>(buf1, F_MID, gn4_w, gn4_b, gn4_ms, alpha, beta);
    k_mma<true, true, false><<<gmid, 256, SMEM_SZ>>>(buf1, whi + WO4, wlo + WO4, lin4_b,
        alpha, beta, batch, a4, buf1, buf2, N_NODES, F_MID, F_MID);
    // stage 5: out = prelu(gn5(x3)) @ W5^T + b5   (Nout=512)
    k_segstats<<<dim3(NGRAPH, 1), 256>>>(buf2, F_MID, gn5_w, gn5_b, gn5_ms, alpha, beta);
    k_mma<true, false, false><<<gout, 256, SMEM_SZ>>>(buf2, whi + WO5, wlo + WO5, lin5_b,
        alpha, beta, batch, a5, nullptr, out, N_NODES, F_MID, F_IN);

    (void)in_sizes; (void)n_in; (void)out_size;
}

// round 8
// speedup vs baseline: 3.6910x; 2.0613x over previous
#include <cuda_runtime.h>
#include <cuda_bf16.h>
#include <cstdint>
#include <cstddef>

#define N_NODES 100000
#define F_IN    512
#define F_MID   256
#define NGRAPH  256
#define EPS_GN  1e-5f
#define GRID_M  ((N_NODES + 127) / 128)
#define NPAD    (GRID_M * 128)

// ---------------- device scratch ----------------
__device__ float g_buf1[(size_t)N_NODES * F_MID];
__device__ float g_buf2[(size_t)N_NODES * F_MID];
__device__ float g_alpha[NGRAPH * F_IN];
__device__ float g_beta [NGRAPH * F_IN];
__device__ int   g_segstart[NGRAPH + 1];
__device__ float g_part[2 * 256 * F_MID];
__device__ int   g_is64;

// prep'd A (normalized, prelu'd, bf16 hi/lo), padded rows
__device__ __align__(16) __nv_bfloat16 g_ah[(size_t)NPAD * F_IN];
__device__ __align__(16) __nv_bfloat16 g_al[(size_t)NPAD * F_IN];

#define W_TOT (F_MID*F_IN + 3*F_MID*F_MID + F_IN*F_MID)
__device__ __align__(16) __nv_bfloat16 g_whi[W_TOT];
__device__ __align__(16) __nv_bfloat16 g_wlo[W_TOT];
#define WO1 0
#define WO2 (F_MID*F_IN)
#define WO3 (WO2 + F_MID*F_MID)
#define WO4 (WO3 + F_MID*F_MID)
#define WO5 (WO4 + F_MID*F_MID)

// ---------------- helpers ----------------
__device__ __forceinline__ uint32_t smem_u32(const void* p) {
    uint32_t a;
    asm("{ .reg .u64 t; cvta.to.shared.u64 t, %1; cvt.u32.u64 %0, t; }" : "=r"(a) : "l"(p));
    return a;
}
#define CP_ASYNC16(dst, src) \
    asm volatile("cp.async.cg.shared.global [%0], [%1], 16;" :: "r"(dst), "l"(src) : "memory")
#define CP_COMMIT()  asm volatile("cp.async.commit_group;" ::: "memory")
#define CP_WAIT1()   asm volatile("cp.async.wait_group 1;" ::: "memory")

#define LDSM_X4(r0,r1,r2,r3,addr) \
    asm volatile("ldmatrix.sync.aligned.m8n8.x4.shared.b16 {%0,%1,%2,%3}, [%4];" \
        : "=r"(r0),"=r"(r1),"=r"(r2),"=r"(r3) : "r"(addr))
#define LDSM_X2(r0,r1,addr) \
    asm volatile("ldmatrix.sync.aligned.m8n8.x2.shared.b16 {%0,%1}, [%2];" \
        : "=r"(r0),"=r"(r1) : "r"(addr))
#define MMA16816(c, a0,a1,a2,a3, b0,b1) \
    asm volatile("mma.sync.aligned.m16n8k16.row.col.f32.bf16.bf16.f32 " \
        "{%0,%1,%2,%3}, {%4,%5,%6,%7}, {%8,%9}, {%0,%1,%2,%3};" \
        : "+f"((c)[0]),"+f"((c)[1]),"+f"((c)[2]),"+f"((c)[3]) \
        : "r"(a0),"r"(a1),"r"(a2),"r"(a3), "r"(b0),"r"(b1))

__device__ __forceinline__ uint32_t pack_bf2(float a, float b) {
    __nv_bfloat162 p;
    p.x = __float2bfloat16_rn(a);
    p.y = __float2bfloat16_rn(b);
    return *reinterpret_cast<uint32_t*>(&p);
}

// ---------------- batch dtype detection ----------------
__global__ void k_detect(const int* b32, int n64) {
    __shared__ int found;
    if (threadIdx.x == 0) found = 0;
    __syncthreads();
    for (int i = threadIdx.x; i < n64; i += blockDim.x)
        if (b32[2 * i + 1] != 0) { found = 1; break; }
    __syncthreads();
    if (threadIdx.x == 0) g_is64 = found ? 0 : 1;
}
__device__ __forceinline__ int get_batch(const void* bp, int r) {
    return g_is64 ? (int)((const long long*)bp)[r] : ((const int*)bp)[r];
}

__global__ void k_segbounds(const void* bp, int n) {
    int g = threadIdx.x;
    if (g > NGRAPH) return;
    if (g == NGRAPH) { g_segstart[g] = n; return; }
    int lo = 0, hi = n;
    while (lo < hi) { int mid = (lo + hi) >> 1; if (get_batch(bp, mid) < g) lo = mid + 1; else hi = mid; }
    g_segstart[g] = lo;
}

// ---------------- per-graph stats -> folded affine ----------------
__global__ void k_segstats(const float* __restrict__ x, int F,
                           const float* __restrict__ w, const float* __restrict__ b,
                           const float* __restrict__ ms,
                           float* __restrict__ alpha, float* __restrict__ beta) {
    int g = blockIdx.x;
    int f = blockIdx.y * blockDim.x + threadIdx.x;
    int s = g_segstart[g], e = g_segstart[g + 1];
    float sum = 0.f, sq = 0.f;
    for (int r = s; r < e; r++) { float v = x[(size_t)r * F + f]; sum += v; sq += v * v; }
    float cnt = fmaxf((float)(e - s), 1.f);
    float m = sum / cnt, ex2 = sq / cnt, msv = ms[f];
    float var = ex2 - m * m * msv * (2.f - msv);
    float rstd = rsqrtf(var + EPS_GN);
    float wa = w[f] * rstd;
    alpha[g * F + f] = wa;
    beta [g * F + f] = b[f] - wa * msv * m;
}

// ---------------- global stats (gn3) ----------------
__global__ void k_gstats_acc(const float* __restrict__ x, int N) {
    int f = threadIdx.x;
    int chunk = (N + gridDim.x - 1) / gridDim.x;
    int r0 = blockIdx.x * chunk, r1 = min(r0 + chunk, N);
    float sum = 0.f, sq = 0.f;
    for (int r = r0; r < r1; r++) { float v = x[(size_t)r * F_MID + f]; sum += v; sq += v * v; }
    g_part[blockIdx.x * F_MID + f] = sum;
    g_part[256 * F_MID + blockIdx.x * F_MID + f] = sq;
}
__global__ void k_gstats_fin(const float* __restrict__ w, const float* __restrict__ b,
                             const float* __restrict__ ms,
                             float* __restrict__ alpha, float* __restrict__ beta, float cnt) {
    int f = threadIdx.x;
    float sum = 0.f, sq = 0.f;
    for (int i = 0; i < 256; i++) { sum += g_part[i * F_MID + f]; sq += g_part[256 * F_MID + i * F_MID + f]; }
    float m = sum / cnt, ex2 = sq / cnt, msv = ms[f];
    float var = ex2 - m * m * msv * (2.f - msv);
    float rstd = rsqrtf(var + EPS_GN);
    float wa = w[f] * rstd;
    alpha[f] = wa;
    beta [f] = b[f] - wa * msv * m;
}

// ---------------- weight split fp32 -> bf16 hi/lo ----------------
__global__ void k_wsplit(const float* __restrict__ W, __nv_bfloat16* hi, __nv_bfloat16* lo, int n) {
    int i = blockIdx.x * blockDim.x + threadIdx.x;
    if (i >= n) return;
    float v = W[i];
    __nv_bfloat16 h = __float2bfloat16_rn(v);
    hi[i] = h;
    lo[i] = __float2bfloat16_rn(v - __bfloat162float(h));
}

// ---------------- A prep: norm (+prelu) + bf16 split -> padded global ----------------
template<bool PRELU, bool GLOBALN>
__global__ void __launch_bounds__(256)
k_prep(const float* __restrict__ X,
       const float* __restrict__ alpha, const float* __restrict__ beta,
       const void* __restrict__ batchp, const float* __restrict__ slope_ptr,
       __nv_bfloat16* __restrict__ hi, __nv_bfloat16* __restrict__ lo,
       int N, int K) {
    int idx = blockIdx.x * blockDim.x + threadIdx.x;   // one float4 each
    int kq = idx & ((K >> 2) - 1);
    int row = idx / (K >> 2);
    if (row >= NPAD) return;
    int kk = kq * 4;
    float4 v = make_float4(0.f, 0.f, 0.f, 0.f);
    if (row < N) {
        float slope = PRELU ? *slope_ptr : 0.f;
        int g = GLOBALN ? 0 : get_batch(batchp, row);
        float4 xv = *(const float4*)(X + (size_t)row * K + kk);
        float4 al = *(const float4*)(alpha + (size_t)g * K + kk);
        float4 be = *(const float4*)(beta  + (size_t)g * K + kk);
        v.x = fmaf(xv.x, al.x, be.x); v.y = fmaf(xv.y, al.y, be.y);
        v.z = fmaf(xv.z, al.z, be.z); v.w = fmaf(xv.w, al.w, be.w);
        if (PRELU) {
            v.x = v.x >= 0.f ? v.x : slope * v.x;
            v.y = v.y >= 0.f ? v.y : slope * v.y;
            v.z = v.z >= 0.f ? v.z : slope * v.z;
            v.w = v.w >= 0.f ? v.w : slope * v.w;
        }
    }
    float hx = __bfloat162float(__float2bfloat16_rn(v.x));
    float hy = __bfloat162float(__float2bfloat16_rn(v.y));
    float hz = __bfloat162float(__float2bfloat16_rn(v.z));
    float hw = __bfloat162float(__float2bfloat16_rn(v.w));
    uint2 hv, lv;
    hv.x = pack_bf2(v.x, v.y);           hv.y = pack_bf2(v.z, v.w);
    lv.x = pack_bf2(v.x - hx, v.y - hy); lv.y = pack_bf2(v.z - hz, v.w - hw);
    *(uint2*)(hi + (size_t)row * K + kk) = hv;
    *(uint2*)(lo + (size_t)row * K + kk) = lv;
}

// ---------------- async-pipelined HMMA GEMM ----------------
// CTA 128x128, BK=64, 3-stage cp.async pipeline, 8 warps (2Mx4N), warp tile 64x32.
// Stage layout (64KB): Ahi 16K | Alo 16K | Bhi 16K | Blo 16K.
// Row = 128 B (64 bf16), XOR swizzle on 16B units: off = row*128 + ((kg ^ (row&7))<<4).
#define STG_B   65536
#define SMEM_SZ (3 * STG_B)

template<bool RESID>
__global__ void __launch_bounds__(256, 1)
k_mma(const __nv_bfloat16* __restrict__ Ahi, const __nv_bfloat16* __restrict__ Alo,
      const __nv_bfloat16* __restrict__ Whi, const __nv_bfloat16* __restrict__ Wlo,
      const float* __restrict__ bias,
      const float* __restrict__ resid, float* __restrict__ out,
      int N, int K, int Nout) {
    extern __shared__ char sm[];
    uint32_t sbase = smem_u32(sm);

    int tid = threadIdx.x, wid = tid >> 5, lane = tid & 31;
    int bm0 = blockIdx.x * 128, bn0 = blockIdx.y * 128;
    int NC = K >> 6;
    int wm = (wid >> 2) * 64;
    int wn = (wid & 3) * 32;

    float acc[4][4][4];
    #pragma unroll
    for (int i = 0; i < 4; i++)
        #pragma unroll
        for (int j = 0; j < 4; j++)
            #pragma unroll
            for (int q = 0; q < 4; q++) acc[i][j][q] = 0.f;

    // per-thread fill coords: 1024 16B-chunks per array per stage, 4 per thread
    int frow = tid >> 3;          // 0..31 (+32*i)
    int fkg  = tid & 7;           // 0..7

    auto issue = [&](int c) {
        if (c < NC) {
            int kt = c << 6;
            uint32_t base = sbase + (uint32_t)(c % 3) * STG_B;
            #pragma unroll
            for (int i = 0; i < 4; i++) {
                int row = frow + i * 32;
                uint32_t sw = (uint32_t)(row * 128 + (((fkg ^ (row & 7))) << 4));
                const __nv_bfloat16* sa = Ahi + (size_t)(bm0 + row) * K + kt + fkg * 8;
                const __nv_bfloat16* sl = Alo + (size_t)(bm0 + row) * K + kt + fkg * 8;
                const __nv_bfloat16* sb = Whi + (size_t)(bn0 + row) * K + kt + fkg * 8;
                const __nv_bfloat16* sbl= Wlo + (size_t)(bn0 + row) * K + kt + fkg * 8;
                CP_ASYNC16(base + sw,                 sa);
                CP_ASYNC16(base + 16384 + sw,         sl);
                CP_ASYNC16(base + 32768 + sw,         sb);
                CP_ASYNC16(base + 49152 + sw,         sbl);
            }
        }
        CP_COMMIT();
    };

    issue(0);
    issue(1);

    for (int c = 0; c < NC; c++) {
        CP_WAIT1();
        __syncthreads();
        issue(c + 2);

        uint32_t base = sbase + (uint32_t)(c % 3) * STG_B;
        #pragma unroll
        for (int kk = 0; kk < 64; kk += 16) {
            uint32_t ah[4][4], alr[4][4], bh[4][2], bl[4][2];
            #pragma unroll
            for (int mt = 0; mt < 4; mt++) {
                int row = wm + mt * 16 + (lane & 15);
                int kb = (kk >> 3) + (lane >> 4);
                uint32_t ad = base + (uint32_t)(row * 128 + ((kb ^ (row & 7)) << 4));
                LDSM_X4(ah[mt][0], ah[mt][1], ah[mt][2], ah[mt][3], ad);
                LDSM_X4(alr[mt][0], alr[mt][1], alr[mt][2], alr[mt][3], ad + 16384);
            }
            #pragma unroll
            for (int nt = 0; nt < 4; nt++) {
                int row = wn + nt * 8 + (lane & 7);
                int kb = (kk >> 3) + ((lane >> 3) & 1);
                uint32_t bd = base + 32768 + (uint32_t)(row * 128 + ((kb ^ (row & 7)) << 4));
                LDSM_X2(bh[nt][0], bh[nt][1], bd);
                LDSM_X2(bl[nt][0], bl[nt][1], bd + 16384);
            }
            #pragma unroll
            for (int mt = 0; mt < 4; mt++)
                #pragma unroll
                for (int nt = 0; nt < 4; nt++) {
                    MMA16816(acc[mt][nt], ah[mt][0], ah[mt][1], ah[mt][2], ah[mt][3], bh[nt][0], bh[nt][1]);
                    MMA16816(acc[mt][nt], ah[mt][0], ah[mt][1], ah[mt][2], ah[mt][3], bl[nt][0], bl[nt][1]);
                    MMA16816(acc[mt][nt], alr[mt][0], alr[mt][1], alr[mt][2], alr[mt][3], bh[nt][0], bh[nt][1]);
                }
        }
        __syncthreads();
    }

    // ---- epilogue ----
    #pragma unroll
    for (int mt = 0; mt < 4; mt++) {
        int r0 = bm0 + wm + mt * 16 + (lane >> 2);
        #pragma unroll
        for (int nt = 0; nt < 4; nt++) {
            int n = bn0 + wn + nt * 8 + 2 * (lane & 3);
            float2 bv = *(const float2*)(bias + n);
            float c0 = acc[mt][nt][0] + bv.x;
            float c1 = acc[mt][nt][1] + bv.y;
            float c2 = acc[mt][nt][2] + bv.x;
            float c3 = acc[mt][nt][3] + bv.y;
            if (r0 < N) {
                if (RESID) {
                    float2 rv = *(const float2*)(resid + (size_t)r0 * Nout + n);
                    c0 = (c0 + rv.x) * 0.5f; c1 = (c1 + rv.y) * 0.5f;
                }
                float2 o; o.x = c0; o.y = c1;
                *(float2*)(out + (size_t)r0 * Nout + n) = o;
            }
            int r1 = r0 + 8;
            if (r1 < N) {
                if (RESID) {
                    float2 rv = *(const float2*)(resid + (size_t)r1 * Nout + n);
                    c2 = (c2 + rv.x) * 0.5f; c3 = (c3 + rv.y) * 0.5f;
                }
                float2 o; o.x = c2; o.y = c3;
                *(float2*)(out + (size_t)r1 * Nout + n) = o;
            }
        }
    }
}

// ---------------- launch ----------------
extern "C" void kernel_launch(void* const* d_in, const int* in_sizes, int n_in,
                              void* d_out, int out_size) {
    const float* x     = (const float*)d_in[0];
    const void*  batch = d_in[1];
    const float* gn1_w = (const float*)d_in[2],  *gn1_b = (const float*)d_in[3],  *gn1_ms = (const float*)d_in[4];
    const float* gn2_w = (const float*)d_in[5],  *gn2_b = (const float*)d_in[6],  *gn2_ms = (const float*)d_in[7];
    const float* gn3_w = (const float*)d_in[8],  *gn3_b = (const float*)d_in[9],  *gn3_ms = (const float*)d_in[10];
    const float* gn4_w = (const float*)d_in[11], *gn4_b = (const float*)d_in[12], *gn4_ms = (const float*)d_in[13];
    const float* gn5_w = (const float*)d_in[14], *gn5_b = (const float*)d_in[15], *gn5_ms = (const float*)d_in[16];
    const float* lin1_W = (const float*)d_in[17], *lin1_b = (const float*)d_in[18];
    const float* lin2_W = (const float*)d_in[19], *lin2_b = (const float*)d_in[20];
    const float* lin3_W = (const float*)d_in[21], *lin3_b = (const float*)d_in[22];
    const float* lin4_W = (const float*)d_in[23], *lin4_b = (const float*)d_in[24];
    const float* lin5_W = (const float*)d_in[25], *lin5_b = (const float*)d_in[26];
    const float* a2 = (const float*)d_in[27];
    const float* a3 = (const float*)d_in[28];
    const float* a4 = (const float*)d_in[29];
    const float* a5 = (const float*)d_in[30];
    float* out = (float*)d_out;

    float *buf1, *buf2, *alpha, *beta;
    __nv_bfloat16 *whi, *wlo, *ah, *al;
    cudaGetSymbolAddress((void**)&buf1,  g_buf1);
    cudaGetSymbolAddress((void**)&buf2,  g_buf2);
    cudaGetSymbolAddress((void**)&alpha, g_alpha);
    cudaGetSymbolAddress((void**)&beta,  g_beta);
    cudaGetSymbolAddress((void**)&whi,   g_whi);
    cudaGetSymbolAddress((void**)&wlo,   g_wlo);
    cudaGetSymbolAddress((void**)&ah,    g_ah);
    cudaGetSymbolAddress((void**)&al,    g_al);

    cudaFuncSetAttribute(k_mma<false>, cudaFuncAttributeMaxDynamicSharedMemorySize, SMEM_SZ);
    cudaFuncSetAttribute(k_mma<true >, cudaFuncAttributeMaxDynamicSharedMemorySize, SMEM_SZ);

    k_detect<<<1, 1024>>>((const int*)batch, N_NODES / 2);
    k_segbounds<<<1, NGRAPH + 1>>>(batch, N_NODES);

    k_wsplit<<<(F_MID * F_IN  + 255) / 256, 256>>>(lin1_W, whi + WO1, wlo + WO1, F_MID * F_IN);
    k_wsplit<<<(F_MID * F_MID + 255) / 256, 256>>>(lin2_W, whi + WO2, wlo + WO2, F_MID * F_MID);
    k_wsplit<<<(F_MID * F_MID + 255) / 256, 256>>>(lin3_W, whi + WO3, wlo + WO3, F_MID * F_MID);
    k_wsplit<<<(F_MID * F_MID + 255) / 256, 256>>>(lin4_W, whi + WO4, wlo + WO4, F_MID * F_MID);
    k_wsplit<<<(F_IN  * F_MID + 255) / 256, 256>>>(lin5_W, whi + WO5, wlo + WO5, F_IN * F_MID);

    dim3 gmid(GRID_M, 2), gout(GRID_M, 4);
    int pgrid1 = (NPAD * (F_IN  / 4) + 255) / 256;
    int pgridm = (NPAD * (F_MID / 4) + 255) / 256;

    // stage 1: x1 = gn1(x) @ W1^T + b1   (K=512)
    k_segstats<<<dim3(NGRAPH, 2), 256>>>(x, F_IN, gn1_w, gn1_b, gn1_ms, alpha, beta);
    k_prep<false, false><<<pgrid1, 256>>>(x, alpha, beta, batch, nullptr, ah, al, N_NODES, F_IN);
    k_mma<false><<<gmid, 256, SMEM_SZ>>>(ah, al, whi + WO1, wlo + WO1, lin1_b,
        nullptr, buf1, N_NODES, F_IN, F_MID);
    // stage 2: h = prelu(gn2(x1)) @ W2^T + b2
    k_segstats<<<dim3(NGRAPH, 1), 256>>>(buf1, F_MID, gn2_w, gn2_b, gn2_ms, alpha, beta);
    k_prep<true, false><<<pgridm, 256>>>(buf1, alpha, beta, batch, a2, ah, al, N_NODES, F_MID);
    k_mma<false><<<gmid, 256, SMEM_SZ>>>(ah, al, whi + WO2, wlo + WO2, lin2_b,
        nullptr, buf2, N_NODES, F_MID, F_MID);
    // stage 3 (global norm): x2 = (prelu(gn3g(h)) @ W3^T + b3 + x1)/2 -> buf1
    k_gstats_acc<<<256, F_MID>>>(buf2, N_NODES);
    k_gstats_fin<<<1, F_MID>>>(gn3_w, gn3_b, gn3_ms, alpha, beta, (float)N_NODES);
    k_prep<true, true><<<pgridm, 256>>>(buf2, alpha, beta, nullptr, a3, ah, al, N_NODES, F_MID);
    k_mma<true><<<gmid, 256, SMEM_SZ>>>(ah, al, whi + WO3, wlo + WO3, lin3_b,
        buf1, buf1, N_NODES, F_MID, F_MID);
    // stage 4: x3 = (prelu(gn4(x2)) @ W4^T + b4 + x2)/2 -> buf2
    k_segstats<<<dim3(NGRAPH, 1), 256>>>(buf1, F_MID, gn4_w, gn4_b, gn4_ms, alpha, beta);
    k_prep<true, false><<<pgridm, 256>>>(buf1, alpha, beta, batch, a4, ah, al, N_NODES, F_MID);
    k_mma<true><<<gmid, 256, SMEM_SZ>>>(ah, al, whi + WO4, wlo + WO4, lin4_b,
        buf1, buf2, N_NODES, F_MID, F_MID);
    // stage 5: out = prelu(gn5(x3)) @ W5^T + b5   (Nout=512)
    k_segstats<<<dim3(NGRAPH, 1), 256>>>(buf2, F_MID, gn5_w, gn5_b, gn5_ms, alpha, beta);
    k_prep<true, false><<<pgridm, 256>>>(buf2, alpha, beta, batch, a5, ah, al, N_NODES, F_MID);
    k_mma<false><<<gout, 256, SMEM_SZ>>>(ah, al, whi + WO5, wlo + WO5, lin5_b,
        nullptr, out, N_NODES, F_MID, F_IN);

    (void)in_sizes; (void)n_in; (void)out_size;
}